// round 8
// baseline (speedup 1.0000x reference)
#include <cuda_runtime.h>
#include <cuda_bf16.h>

#define BB      32
#define SS      64
#define DD      8
#define NEIDX   512
#define NBINS   (NEIDX * BB)   // 16384 (eidx, c0) bins
#define EMAX    150000
#define NW      4              // warps per CTA in fused kernel
#define SPLIT   4              // CTAs per eidx
#define CPB     (BB / SPLIT)   // batch rows (c0s) per CTA = 8

// ---------------- device scratch ----------------
__device__ int g_bin_cnt[NBINS];
__device__ int g_bin_start[NBINS + 1];
__device__ int g_cursor[NBINS];
__device__ int g_sorted[EMAX];           // packed: c0 | (c1<<5)

// ---------------- K0: zero ----------------
__global__ void k_zero() {
    int t = blockIdx.x * blockDim.x + threadIdx.x;
    if (t < NBINS) g_bin_cnt[t] = 0;
}

// ---------------- K1: histogram over 16K bins (spread global atomics) ------
__global__ __launch_bounds__(512) void k_hist(const int4* __restrict__ inc, int E) {
    int i = blockIdx.x * blockDim.x + threadIdx.x;
    if (i < E) {
        int4 r = inc[i];
        atomicAdd(&g_bin_cnt[(r.z * DD + r.w) * BB + r.x], 1);
    }
}

// ---------------- K2: scan of 16K bins (1 CTA, 512 threads x 32 serial) ----
__global__ __launch_bounds__(512) void k_scan() {
    __shared__ int s[512];
    int t = threadIdx.x;
    int base = t * 32;
    int loc[32];
    int run = 0;
    #pragma unroll
    for (int k = 0; k < 32; k++) {
        loc[k] = run;                    // local exclusive prefix
        run += g_bin_cnt[base + k];
    }
    s[t] = run;
    __syncthreads();
    for (int off = 1; off < 512; off <<= 1) {
        int x = (t >= off) ? s[t - off] : 0;
        __syncthreads();
        s[t] += x;
        __syncthreads();
    }
    int excl = s[t] - run;
    #pragma unroll
    for (int k = 0; k < 32; k++) {
        g_bin_start[base + k] = excl + loc[k];
        g_cursor[base + k]    = excl + loc[k];
    }
    if (t == 511) g_bin_start[NBINS] = s[511];
}

// ---------------- K3: scatter (spread global atomics) ----------------
__global__ __launch_bounds__(512) void k_scatter(const int4* __restrict__ inc, int E) {
    int i = blockIdx.x * blockDim.x + threadIdx.x;
    if (i < E) {
        int4 r = inc[i];
        int b = (r.z * DD + r.w) * BB + r.x;
        int pos = atomicAdd(&g_cursor[b], 1);
        g_sorted[pos] = r.x | (r.y << 5);
    }
}

// ---------------- K4: fused edge MLP + segment mean + output MLP ----------------
// Grid = NEIDX*SPLIT. CTA (e, q) owns batch rows c0 in [q*8, q*8+8).
// Edges arrive globally sorted by (e, c0); segment bounds from g_bin_start.
// Lane = output channel; weights in registers; 4 edges in flight; register
// accumulator with flush-on-c0-change into SMEM.
__global__ __launch_bounds__(NW * 32) void k_fused(
    const float* __restrict__ nodes,
    const float* __restrict__ W0,  const float* __restrict__ b0,
    const float* __restrict__ W1,  const float* __restrict__ b1,
    const float* __restrict__ oW0, const float* __restrict__ ob0,
    const float* __restrict__ oW1, const float* __restrict__ ob1,
    float* __restrict__ out)
{
    __shared__ __align__(16) float s_hb[NW][4][32]; // per-warp h staging
    __shared__ __align__(16) float s_acc[CPB * 32]; // [c0_loc][o]; reused as hh
    __shared__ __align__(16) float s_ef[CPB * 32];
    __shared__ __align__(16) float s_w0t[1024];     // out_core0 transposed [i][o]
    __shared__ __align__(16) float s_w1t[512];      // out_core1 transposed [i][o]
    __shared__ float s_ob0[32], s_ob1[16];

    int bx   = blockIdx.x;
    int e    = bx >> 2;                  // SPLIT = 4
    int q    = bx & 3;
    int c0b  = q * CPB;
    int tid  = threadIdx.x;
    int warp = tid >> 5, lane = tid & 31;
    int c2   = e >> 3;

    // ---- lane's input-MLP weight rows into registers ----
    float w0r[16], w1r[32];
    {
        const float4* p0 = (const float4*)(W0 + e * 512 + lane * 16);
        #pragma unroll
        for (int v4 = 0; v4 < 4; v4++) {
            float4 v = p0[v4];
            w0r[v4*4+0] = v.x; w0r[v4*4+1] = v.y; w0r[v4*4+2] = v.z; w0r[v4*4+3] = v.w;
        }
        const float4* p1 = (const float4*)(W1 + e * 1024 + lane * 32);
        #pragma unroll
        for (int v4 = 0; v4 < 8; v4++) {
            float4 v = p1[v4];
            w1r[v4*4+0] = v.x; w1r[v4*4+1] = v.y; w1r[v4*4+2] = v.z; w1r[v4*4+3] = v.w;
        }
    }
    float rb0 = b0[e * 32 + lane];
    float rb1 = b1[e * 32 + lane];

    for (int t = tid; t < CPB * 32; t += NW * 32) s_acc[t] = 0.f;
    __syncthreads();

    int start = g_bin_start[e * BB + c0b];
    int n     = g_bin_start[e * BB + c0b + CPB] - start;

    // ---- balanced warp chunks over this CTA's edge range ----
    int wbeg = start + (n * warp)     / NW;
    int wend = start + (n * (warp+1)) / NW;
    float (*hb)[32] = s_hb[warp];

    float acc = 0.f;
    int cur = -1;
    for (int j = wbeg; j < wend; j += 4) {
        int pk[4];
        const float4* xp[4];
        #pragma unroll
        for (int k = 0; k < 4; k++) {
            int jj = j + k;
            pk[k] = (jj < wend) ? g_sorted[jj] : -1;
            int c1 = (pk[k] >= 0) ? (pk[k] >> 5) : 0;
            xp[k] = (const float4*)(nodes + (c1 * SS + c2) * 16);
        }

        // layer 1, 4 edges interleaved
        float h[4] = {rb0, rb0, rb0, rb0};
        #pragma unroll
        for (int v4 = 0; v4 < 4; v4++) {
            float4 X[4];
            #pragma unroll
            for (int k = 0; k < 4; k++) X[k] = xp[k][v4];     // uniform LDG.128
            #pragma unroll
            for (int k = 0; k < 4; k++) {
                h[k] = fmaf(w0r[v4*4+0], X[k].x, h[k]);
                h[k] = fmaf(w0r[v4*4+1], X[k].y, h[k]);
                h[k] = fmaf(w0r[v4*4+2], X[k].z, h[k]);
                h[k] = fmaf(w0r[v4*4+3], X[k].w, h[k]);
            }
        }
        #pragma unroll
        for (int k = 0; k < 4; k++) hb[k][lane] = fmaxf(h[k], 0.f);
        __syncwarp();

        // layer 2, 4 edges interleaved
        float g[4] = {rb1, rb1, rb1, rb1};
        #pragma unroll
        for (int v4 = 0; v4 < 8; v4++) {
            float4 H[4];
            #pragma unroll
            for (int k = 0; k < 4; k++) H[k] = ((const float4*)hb[k])[v4];
            #pragma unroll
            for (int k = 0; k < 4; k++) {
                g[k] = fmaf(w1r[v4*4+0], H[k].x, g[k]);
                g[k] = fmaf(w1r[v4*4+1], H[k].y, g[k]);
                g[k] = fmaf(w1r[v4*4+2], H[k].z, g[k]);
                g[k] = fmaf(w1r[v4*4+3], H[k].w, g[k]);
            }
        }
        __syncwarp();

        // register accumulate, flush on c0 change
        #pragma unroll
        for (int k = 0; k < 4; k++) {
            if (pk[k] >= 0) {
                int c0 = pk[k] & 31;
                if (c0 != cur) {
                    if (cur >= 0) atomicAdd(&s_acc[(cur - c0b) * 32 + lane], acc);
                    acc = 0.f;
                    cur = c0;
                }
                acc += fmaxf(g[k], 0.f);
            }
        }
    }
    if (cur >= 0) atomicAdd(&s_acc[(cur - c0b) * 32 + lane], acc);
    __syncthreads();

    // ---- stage output weights (transposed) ----
    for (int t = tid; t < 1024; t += NW * 32) {
        int o = t >> 5, i = t & 31;
        s_w0t[i * 32 + o] = oW0[e * 1024 + t];
    }
    for (int t = tid; t < 512; t += NW * 32) {
        int o = t >> 5, i = t & 31;
        s_w1t[i * 16 + o] = oW1[e * 512 + t];
    }
    if (tid < 32) s_ob0[tid] = ob0[e * 32 + tid];
    if (tid < 16) s_ob1[tid] = ob1[e * 16 + tid];

    // ---- mean over this CTA's 8 segments ----
    for (int t = tid; t < CPB * 32; t += NW * 32) {
        int bl = t >> 5;
        int bin = e * BB + c0b + bl;
        int c = g_bin_start[bin + 1] - g_bin_start[bin];
        s_ef[t] = (c > 0) ? s_acc[t] / (float)c : 0.f;
    }
    __syncthreads();

    // ---- out layer 1 (hh reuses s_acc) ----
    for (int t = tid; t < CPB * 32; t += NW * 32) {
        int bl = t >> 5, o = t & 31;
        float s = s_ob0[o];
        #pragma unroll
        for (int i = 0; i < 32; i++)
            s = fmaf(s_w0t[i * 32 + o], s_ef[bl * 32 + i], s);
        s_acc[t] = fmaxf(s, 0.f);
    }
    __syncthreads();

    // ---- out layer 2 + store ----
    for (int t = tid; t < CPB * 16; t += NW * 32) {
        int bl = t >> 4, o = t & 15;
        float s = s_ob1[o];
        #pragma unroll
        for (int i = 0; i < 32; i++)
            s = fmaf(s_w1t[i * 16 + o], s_acc[bl * 32 + i], s);
        out[((c0b + bl) * NEIDX + e) * 16 + o] = fmaxf(s, 0.f);
    }
}

// ---------------- launch ----------------
extern "C" void kernel_launch(void* const* d_in, const int* in_sizes, int n_in,
                              void* d_out, int out_size) {
    const float* nodes = (const float*)d_in[0];
    const float* ic0   = (const float*)d_in[1];
    const float* ib0   = (const float*)d_in[2];
    const float* ic1   = (const float*)d_in[3];
    const float* ib1   = (const float*)d_in[4];
    const float* oc0   = (const float*)d_in[5];
    const float* ob0   = (const float*)d_in[6];
    const float* oc1   = (const float*)d_in[7];
    const float* ob1   = (const float*)d_in[8];
    const int4*  inc   = (const int4*)d_in[9];
    int E = in_sizes[9] / 4;
    float* out = (float*)d_out;

    k_zero<<<NBINS / 512, 512>>>();
    k_hist<<<(E + 511) / 512, 512>>>(inc, E);
    k_scan<<<1, 512>>>();
    k_scatter<<<(E + 511) / 512, 512>>>(inc, E);
    k_fused<<<NEIDX * SPLIT, NW * 32>>>(nodes, ic0, ib0, ic1, ib1,
                                        oc0, ob0, oc1, ob1, out);
}

// round 9
// speedup vs baseline: 1.0468x; 1.0468x over previous
#include <cuda_runtime.h>
#include <cuda_bf16.h>

#define BB      32
#define SS      64
#define DD      8
#define NEIDX   512
#define NBINS   (NEIDX * BB)   // 16384 (eidx, c0) bins
#define EMAX    150000
#define NW      8              // warps per CTA in fused kernel

// ---------------- device scratch ----------------
__device__ int g_bin_cnt[NBINS];
__device__ int g_bin_start[NBINS + 1];
__device__ int g_cursor[NBINS];
__device__ int g_sorted[EMAX];           // packed: c0 | (c1<<5)

// ---------------- K0: zero ----------------
__global__ void k_zero() {
    int t = blockIdx.x * blockDim.x + threadIdx.x;
    if (t < NBINS) g_bin_cnt[t] = 0;
}

// ---------------- K1: histogram over 16K bins (spread global atomics) ------
__global__ __launch_bounds__(512) void k_hist(const int4* __restrict__ inc, int E) {
    int i = blockIdx.x * blockDim.x + threadIdx.x;
    if (i < E) {
        int4 r = inc[i];
        atomicAdd(&g_bin_cnt[(r.z * DD + r.w) * BB + r.x], 1);
    }
}

// ---------------- K2: scan of 16K bins (1 CTA) ----------------
__global__ __launch_bounds__(512) void k_scan() {
    __shared__ int s[512];
    int t = threadIdx.x;
    int base = t * 32;
    int loc[32];
    int run = 0;
    #pragma unroll
    for (int k = 0; k < 32; k++) {
        loc[k] = run;
        run += g_bin_cnt[base + k];
    }
    s[t] = run;
    __syncthreads();
    for (int off = 1; off < 512; off <<= 1) {
        int x = (t >= off) ? s[t - off] : 0;
        __syncthreads();
        s[t] += x;
        __syncthreads();
    }
    int excl = s[t] - run;
    #pragma unroll
    for (int k = 0; k < 32; k++) {
        g_bin_start[base + k] = excl + loc[k];
        g_cursor[base + k]    = excl + loc[k];
    }
    if (t == 511) g_bin_start[NBINS] = s[511];
}

// ---------------- K3: scatter (spread global atomics) ----------------
__global__ __launch_bounds__(512) void k_scatter(const int4* __restrict__ inc, int E) {
    int i = blockIdx.x * blockDim.x + threadIdx.x;
    if (i < E) {
        int4 r = inc[i];
        int b = (r.z * DD + r.w) * BB + r.x;
        int pos = atomicAdd(&g_cursor[b], 1);
        g_sorted[pos] = r.x | (r.y << 5);
    }
}

// ---------------- K4: fused edge MLP + segment mean + output MLP ----------------
// One CTA per eidx, 8 warps, EDGE-PER-LANE (32 independent x gathers in
// flight per warp). Weights broadcast from SMEM. Edges are c0-sorted within
// the bin; each warp takes a contiguous balanced chunk. Reduce: stage g
// (conflict-free stride-33), then lane=o transposed read with register
// accumulation, flushing to s_acc only on c0 change (sorted -> few flushes).
__global__ __launch_bounds__(NW * 32) void k_fused(
    const float* __restrict__ nodes,
    const float* __restrict__ W0,  const float* __restrict__ b0,
    const float* __restrict__ W1,  const float* __restrict__ b1,
    const float* __restrict__ oW0, const float* __restrict__ ob0,
    const float* __restrict__ oW1, const float* __restrict__ ob1,
    float* __restrict__ out)
{
    __shared__ __align__(16) float sW0[512];          // in_core0 [o][i] 32x16
    __shared__ __align__(16) float sW1[1024];         // in_core1 [o][i] 32x32
    __shared__ __align__(16) float s_stage[NW * 33 * 32]; // per-warp g staging; reused in epilogue
    __shared__ __align__(16) float s_acc[BB * 32];    // [c0][o]; reused as hh
    __shared__ float sb0[32], sb1[32], s_ob0[32], s_ob1[16];

    int e    = blockIdx.x;
    int tid  = threadIdx.x;
    int warp = tid >> 5, lane = tid & 31;
    int c2   = e >> 3;

    for (int t = tid; t < 512;  t += NW * 32) sW0[t] = W0[e * 512 + t];
    for (int t = tid; t < 1024; t += NW * 32) sW1[t] = W1[e * 1024 + t];
    if (tid < 32) { sb0[tid] = b0[e * 32 + tid]; sb1[tid] = b1[e * 32 + tid]; }
    for (int t = tid; t < BB * 32; t += NW * 32) s_acc[t] = 0.f;
    __syncthreads();

    int start = g_bin_start[e * BB];
    int n     = g_bin_start[(e + 1) * BB] - start;

    int wbeg = start + (n * warp)       / NW;
    int wend = start + (n * (warp + 1)) / NW;
    float* ST = s_stage + warp * 33 * 32;

    float racc = 0.f;
    int   rcur = -1;

    for (int j0 = wbeg; j0 < wend; j0 += 32) {
        int j = j0 + lane;
        bool v = (j < wend);
        int pk = v ? g_sorted[j] : -1;
        int c1 = (pk >> 5) & 1023;
        const float4* xp = (const float4*)(nodes + (v ? (c1 * SS + c2) * 16 : 0));
        float4 x0 = xp[0], x1 = xp[1], x2 = xp[2], x3 = xp[3]; // 32 divergent gathers/warp

        // layer 1: h[o] per lane-edge; weights broadcast (uniform address)
        float h[32];
        #pragma unroll
        for (int o = 0; o < 32; o++) {
            const float4* w = (const float4*)(sW0 + o * 16);
            float4 w0 = w[0], w1 = w[1], w2 = w[2], w3 = w[3];
            float s = sb0[o];
            s = fmaf(w0.x, x0.x, s); s = fmaf(w0.y, x0.y, s);
            s = fmaf(w0.z, x0.z, s); s = fmaf(w0.w, x0.w, s);
            s = fmaf(w1.x, x1.x, s); s = fmaf(w1.y, x1.y, s);
            s = fmaf(w1.z, x1.z, s); s = fmaf(w1.w, x1.w, s);
            s = fmaf(w2.x, x2.x, s); s = fmaf(w2.y, x2.y, s);
            s = fmaf(w2.z, x2.z, s); s = fmaf(w2.w, x2.w, s);
            s = fmaf(w3.x, x3.x, s); s = fmaf(w3.y, x3.y, s);
            s = fmaf(w3.z, x3.z, s); s = fmaf(w3.w, x3.w, s);
            h[o] = fmaxf(s, 0.f);
        }

        // layer 2: stage relu(g) at stride 33 (bank (lane+o)%32: conflict-free)
        #pragma unroll 8
        for (int o = 0; o < 32; o++) {
            const float4* w = (const float4*)(sW1 + o * 32);
            float s = sb1[o];
            #pragma unroll
            for (int q = 0; q < 8; q++) {
                float4 ww = w[q];
                s = fmaf(ww.x, h[q * 4 + 0], s);
                s = fmaf(ww.y, h[q * 4 + 1], s);
                s = fmaf(ww.z, h[q * 4 + 2], s);
                s = fmaf(ww.w, h[q * 4 + 3], s);
            }
            ST[lane * 33 + o] = v ? fmaxf(s, 0.f) : 0.f;
        }
        __syncwarp();

        // transposed reduce: lane = o. Independent LDS; register FADD chain;
        // flush to s_acc only when c0 changes (sorted chunk -> rare).
        #pragma unroll
        for (int j2 = 0; j2 < 32; j2++) {
            int pk2 = __shfl_sync(0xffffffffu, pk, j2);
            if (pk2 >= 0) {
                int c02 = pk2 & 31;
                if (c02 != rcur) {
                    if (rcur >= 0) atomicAdd(&s_acc[rcur * 32 + lane], racc);
                    racc = 0.f;
                    rcur = c02;
                }
                racc += ST[j2 * 33 + lane];
            }
        }
        __syncwarp();
    }
    if (rcur >= 0) atomicAdd(&s_acc[rcur * 32 + lane], racc);
    __syncthreads();

    // ---- epilogue: reuse s_stage as w0t / w1t / ef ----
    float* s_w0t = s_stage;              // 1024 floats
    float* s_w1t = s_stage + 1024;       // 512 floats
    float* s_ef  = s_stage + 1536;       // 1024 floats

    for (int t = tid; t < 1024; t += NW * 32) {
        int o = t >> 5, i = t & 31;
        s_w0t[i * 32 + o] = oW0[e * 1024 + t];
    }
    for (int t = tid; t < 512; t += NW * 32) {
        int o = t >> 5, i = t & 31;
        s_w1t[i * 16 + o] = oW1[e * 512 + t];
    }
    if (tid < 32) s_ob0[tid] = ob0[e * 32 + tid];
    if (tid < 16) s_ob1[tid] = ob1[e * 16 + tid];

    for (int t = tid; t < BB * 32; t += NW * 32) {
        int bl = t >> 5;
        int bin = e * BB + bl;
        int c = g_bin_start[bin + 1] - g_bin_start[bin];
        s_ef[t] = (c > 0) ? s_acc[t] / (float)c : 0.f;
    }
    __syncthreads();

    // out layer 1 (hh reuses s_acc)
    for (int t = tid; t < BB * 32; t += NW * 32) {
        int bl = t >> 5, o = t & 31;
        float s = s_ob0[o];
        #pragma unroll
        for (int i = 0; i < 32; i++)
            s = fmaf(s_w0t[i * 32 + o], s_ef[bl * 32 + i], s);
        s_acc[t] = fmaxf(s, 0.f);
    }
    __syncthreads();

    // out layer 2 + store
    for (int t = tid; t < BB * 16; t += NW * 32) {
        int bl = t >> 4, o = t & 15;
        float s = s_ob1[o];
        #pragma unroll
        for (int i = 0; i < 32; i++)
            s = fmaf(s_w1t[i * 16 + o], s_acc[bl * 32 + i], s);
        out[(bl * NEIDX + e) * 16 + o] = fmaxf(s, 0.f);
    }
}

// ---------------- launch ----------------
extern "C" void kernel_launch(void* const* d_in, const int* in_sizes, int n_in,
                              void* d_out, int out_size) {
    const float* nodes = (const float*)d_in[0];
    const float* ic0   = (const float*)d_in[1];
    const float* ib0   = (const float*)d_in[2];
    const float* ic1   = (const float*)d_in[3];
    const float* ib1   = (const float*)d_in[4];
    const float* oc0   = (const float*)d_in[5];
    const float* ob0   = (const float*)d_in[6];
    const float* oc1   = (const float*)d_in[7];
    const float* ob1   = (const float*)d_in[8];
    const int4*  inc   = (const int4*)d_in[9];
    int E = in_sizes[9] / 4;
    float* out = (float*)d_out;

    k_zero<<<NBINS / 512, 512>>>();
    k_hist<<<(E + 511) / 512, 512>>>(inc, E);
    k_scan<<<1, 512>>>();
    k_scatter<<<(E + 511) / 512, 512>>>(inc, E);
    k_fused<<<NEIDX, NW * 32>>>(nodes, ic0, ib0, ic1, ib1,
                                oc0, ob0, oc1, ob1, out);
}

// round 10
// speedup vs baseline: 1.2887x; 1.2310x over previous
#include <cuda_runtime.h>
#include <cuda_bf16.h>

#define BB      32
#define SS      64
#define DD      8
#define NEIDX   512
#define EMAX    150000
#define NW      8              // warps per CTA in fused kernel
#define NBC     128            // binning CTAs

// ---------------- device scratch ----------------
__device__ int g_part[NBC][NEIDX];
__device__ int g_base[NBC][NEIDX];
__device__ int g_bin_start[NEIDX + 1];
__device__ int g_sorted[EMAX];           // packed: c0 | (c1<<5)

// ---------------- K1: per-CTA histogram (smem atomics, plain stores) --------
__global__ __launch_bounds__(512) void k_hist(const int4* __restrict__ inc, int E) {
    __shared__ int sh[NEIDX];
    int tid = threadIdx.x;
    sh[tid] = 0;
    __syncthreads();
    int per = (E + NBC - 1) / NBC;
    int beg = blockIdx.x * per;
    int end = min(beg + per, E);
    for (int i = beg + tid; i < end; i += 512) {
        int4 r = inc[i];
        atomicAdd(&sh[r.z * DD + r.w], 1);
    }
    __syncthreads();
    g_part[blockIdx.x][tid] = sh[tid];
}

// ---------------- K2: scan ----------------
__global__ __launch_bounds__(NEIDX) void k_scan() {
    __shared__ int s[NEIDX];
    int t = threadIdx.x;
    int run = 0;
    #pragma unroll 8
    for (int c = 0; c < NBC; c++) {
        int v = g_part[c][t];
        g_base[c][t] = run;
        run += v;
    }
    s[t] = run;
    __syncthreads();
    for (int off = 1; off < NEIDX; off <<= 1) {
        int x = (t >= off) ? s[t - off] : 0;
        __syncthreads();
        s[t] += x;
        __syncthreads();
    }
    g_bin_start[t + 1] = s[t];
    if (t == 0) g_bin_start[0] = 0;
}

// ---------------- K3: scatter (smem cursors, zero global atomics) ----------
__global__ __launch_bounds__(512) void k_scatter(const int4* __restrict__ inc, int E) {
    __shared__ int sc[NEIDX];
    int tid = threadIdx.x;
    sc[tid] = g_bin_start[tid] + g_base[blockIdx.x][tid];
    __syncthreads();
    int per = (E + NBC - 1) / NBC;
    int beg = blockIdx.x * per;
    int end = min(beg + per, E);
    for (int i = beg + tid; i < end; i += 512) {
        int4 r = inc[i];
        int b = r.z * DD + r.w;
        int pos = atomicAdd(&sc[b], 1);
        g_sorted[pos] = r.x | (r.y << 5);
    }
}

// ---------------- K4: fused edge MLP + segment mean + output MLP ----------------
// One CTA per eidx, 8 warps, edge-per-lane (32 independent gathers in flight).
// In-CTA counting sort by c0 -> sorted s_srt. INTERLEAVED passes (92% lane
// util). Reduce: stride-33 stage + shfl'd keys + register accumulate with
// flush-on-c0-change (few ATOMS).
__global__ __launch_bounds__(NW * 32) void k_fused(
    const float* __restrict__ nodes,
    const float* __restrict__ W0,  const float* __restrict__ b0,
    const float* __restrict__ W1,  const float* __restrict__ b1,
    const float* __restrict__ oW0, const float* __restrict__ ob0,
    const float* __restrict__ oW1, const float* __restrict__ ob1,
    float* __restrict__ out)
{
    __shared__ __align__(16) float sW0[512];              // in_core0 [o][i] 32x16
    __shared__ __align__(16) float sW1[1024];             // in_core1 [o][i] 32x32
    __shared__ __align__(16) float s_stage[NW * 33 * 32]; // staging; reused in epilogue
    __shared__ __align__(16) float s_acc[BB * 32];        // [c0][o]; reused as hh
    __shared__ int   s_srt[768];
    __shared__ int   s_hist[32], s_cur[32];
    __shared__ float sb0[32], sb1[32], s_ob0[32], s_ob1[16];

    int e    = blockIdx.x;
    int tid  = threadIdx.x;
    int warp = tid >> 5, lane = tid & 31;
    int c2   = e >> 3;

    for (int t = tid; t < 512;  t += NW * 32) sW0[t] = W0[e * 512 + t];
    for (int t = tid; t < 1024; t += NW * 32) sW1[t] = W1[e * 1024 + t];
    if (tid < 32) { sb0[tid] = b0[e * 32 + tid]; sb1[tid] = b1[e * 32 + tid]; }
    if (tid < 32) s_hist[tid] = 0;
    for (int t = tid; t < BB * 32; t += NW * 32) s_acc[t] = 0.f;
    __syncthreads();

    // ---- in-CTA counting sort by c0 ----
    int start = g_bin_start[e];
    int n     = g_bin_start[e + 1] - start;

    for (int i = tid; i < n; i += NW * 32)
        atomicAdd(&s_hist[g_sorted[start + i] & 31], 1);
    __syncthreads();
    if (warp == 0) {
        int v = s_hist[lane];
        int x = v;
        #pragma unroll
        for (int off = 1; off < 32; off <<= 1) {
            int y = __shfl_up_sync(0xffffffffu, x, off);
            if (lane >= off) x += y;
        }
        s_cur[lane] = x - v;
    }
    __syncthreads();
    for (int i = tid; i < n; i += NW * 32) {
        int p = g_sorted[start + i];
        int pos = atomicAdd(&s_cur[p & 31], 1);
        s_srt[pos] = p;
    }
    __syncthreads();

    // ---- mainloop: interleaved passes ----
    float* ST = s_stage + warp * 33 * 32;
    float racc = 0.f;
    int   rcur = -1;

    for (int j0 = warp * 32; j0 < n; j0 += NW * 32) {
        int j = j0 + lane;
        bool v = (j < n);
        int pk = v ? s_srt[j] : -1;
        int c1 = (pk >> 5) & 1023;
        const float4* xp = (const float4*)(nodes + (v ? (c1 * SS + c2) * 16 : 0));
        float4 x0 = xp[0], x1 = xp[1], x2 = xp[2], x3 = xp[3];

        // layer 1: h[o] per lane-edge; weights broadcast from SMEM
        float h[32];
        #pragma unroll
        for (int o = 0; o < 32; o++) {
            const float4* w = (const float4*)(sW0 + o * 16);
            float4 w0 = w[0], w1 = w[1], w2 = w[2], w3 = w[3];
            float s = sb0[o];
            s = fmaf(w0.x, x0.x, s); s = fmaf(w0.y, x0.y, s);
            s = fmaf(w0.z, x0.z, s); s = fmaf(w0.w, x0.w, s);
            s = fmaf(w1.x, x1.x, s); s = fmaf(w1.y, x1.y, s);
            s = fmaf(w1.z, x1.z, s); s = fmaf(w1.w, x1.w, s);
            s = fmaf(w2.x, x2.x, s); s = fmaf(w2.y, x2.y, s);
            s = fmaf(w2.z, x2.z, s); s = fmaf(w2.w, x2.w, s);
            s = fmaf(w3.x, x3.x, s); s = fmaf(w3.y, x3.y, s);
            s = fmaf(w3.z, x3.z, s); s = fmaf(w3.w, x3.w, s);
            h[o] = fmaxf(s, 0.f);
        }

        // layer 2: stage relu(g) at stride 33 (conflict-free)
        #pragma unroll 8
        for (int o = 0; o < 32; o++) {
            const float4* w = (const float4*)(sW1 + o * 32);
            float s = sb1[o];
            #pragma unroll
            for (int q = 0; q < 8; q++) {
                float4 ww = w[q];
                s = fmaf(ww.x, h[q * 4 + 0], s);
                s = fmaf(ww.y, h[q * 4 + 1], s);
                s = fmaf(ww.z, h[q * 4 + 2], s);
                s = fmaf(ww.w, h[q * 4 + 3], s);
            }
            ST[lane * 33 + o] = v ? fmaxf(s, 0.f) : 0.f;
        }
        __syncwarp();

        // transposed reduce: lane = o; flush only on c0 change (sorted)
        #pragma unroll
        for (int j2 = 0; j2 < 32; j2++) {
            int pk2 = __shfl_sync(0xffffffffu, pk, j2);
            if (pk2 >= 0) {
                int c02 = pk2 & 31;
                if (c02 != rcur) {
                    if (rcur >= 0) atomicAdd(&s_acc[rcur * 32 + lane], racc);
                    racc = 0.f;
                    rcur = c02;
                }
                racc += ST[j2 * 33 + lane];
            }
        }
        __syncwarp();
    }
    if (rcur >= 0) atomicAdd(&s_acc[rcur * 32 + lane], racc);
    __syncthreads();

    // ---- epilogue: reuse s_stage ----
    float* s_w0t = s_stage;              // 1024 floats
    float* s_w1t = s_stage + 1024;       // 512
    float* s_ef  = s_stage + 1536;       // 1024

    for (int t = tid; t < 1024; t += NW * 32) {
        int o = t >> 5, i = t & 31;
        s_w0t[i * 32 + o] = oW0[e * 1024 + t];
    }
    for (int t = tid; t < 512; t += NW * 32) {
        int o = t >> 5, i = t & 31;
        s_w1t[i * 16 + o] = oW1[e * 512 + t];
    }
    if (tid < 32) s_ob0[tid] = ob0[e * 32 + tid];
    if (tid < 16) s_ob1[tid] = ob1[e * 16 + tid];

    for (int t = tid; t < BB * 32; t += NW * 32) {
        int bl = t >> 5;
        int c = s_hist[bl];
        s_ef[t] = (c > 0) ? s_acc[t] / (float)c : 0.f;
    }
    __syncthreads();

    // out layer 1 (hh reuses s_acc)
    for (int t = tid; t < BB * 32; t += NW * 32) {
        int bl = t >> 5, o = t & 31;
        float s = s_ob0[o];
        #pragma unroll
        for (int i = 0; i < 32; i++)
            s = fmaf(s_w0t[i * 32 + o], s_ef[bl * 32 + i], s);
        s_acc[t] = fmaxf(s, 0.f);
    }
    __syncthreads();

    // out layer 2 + store
    for (int t = tid; t < BB * 16; t += NW * 32) {
        int bl = t >> 4, o = t & 15;
        float s = s_ob1[o];
        #pragma unroll
        for (int i = 0; i < 32; i++)
            s = fmaf(s_w1t[i * 16 + o], s_acc[bl * 32 + i], s);
        out[(bl * NEIDX + e) * 16 + o] = fmaxf(s, 0.f);
    }
}

// ---------------- launch ----------------
extern "C" void kernel_launch(void* const* d_in, const int* in_sizes, int n_in,
                              void* d_out, int out_size) {
    const float* nodes = (const float*)d_in[0];
    const float* ic0   = (const float*)d_in[1];
    const float* ib0   = (const float*)d_in[2];
    const float* ic1   = (const float*)d_in[3];
    const float* ib1   = (const float*)d_in[4];
    const float* oc0   = (const float*)d_in[5];
    const float* ob0   = (const float*)d_in[6];
    const float* oc1   = (const float*)d_in[7];
    const float* ob1   = (const float*)d_in[8];
    const int4*  inc   = (const int4*)d_in[9];
    int E = in_sizes[9] / 4;
    float* out = (float*)d_out;

    k_hist<<<NBC, 512>>>(inc, E);
    k_scan<<<1, NEIDX>>>();
    k_scatter<<<NBC, 512>>>(inc, E);
    k_fused<<<NEIDX, NW * 32>>>(nodes, ic0, ib0, ic1, ib1,
                                oc0, ob0, oc1, ob1, out);
}